// round 2
// baseline (speedup 1.0000x reference)
#include <cuda_runtime.h>
#include <cstdint>
#include <climits>

#define T_STEPS 200
#define B_SZ    256
#define IN_SZ   784
#define N_SZ    400

#define ALPHA      0.9f
#define BETA       0.8f
#define THRESH     1.0f
#define BETA_PLUS  0.9f
#define BETA_MINUS 0.9f
#define A_PLUS     1e-3f
#define A_MINUS    1e-3f
#define LI_STR     0.1f

// ---------------- persistent device state ----------------
__device__ float g_Wt[IN_SZ * N_SZ];   // W transposed: Wt[k*N + n] = W[n, k]
__device__ float g_syn[B_SZ * N_SZ];
__device__ float g_mem[B_SZ * N_SZ];
__device__ float g_post[B_SZ * N_SZ];
__device__ float g_tr[B_SZ * IN_SZ];   // pre-synaptic trace (tr_t, BEFORE img_t)
__device__ int   g_win[B_SZ];
__device__ int   g_flag[T_STEPS];

// ---------------- init: transpose W, zero state ----------------
__global__ void k_init(const float* __restrict__ W) {
    int idx = blockIdx.x * blockDim.x + threadIdx.x;
    int stride = gridDim.x * blockDim.x;
    for (int j = idx; j < IN_SZ * N_SZ; j += stride) {
        int k = j / N_SZ, n = j % N_SZ;
        g_Wt[j] = W[n * IN_SZ + k];
    }
    for (int j = idx; j < B_SZ * N_SZ; j += stride) {
        g_syn[j] = 0.f; g_mem[j] = 0.f; g_post[j] = 0.f;
    }
    for (int j = idx; j < B_SZ * IN_SZ; j += stride) g_tr[j] = 0.f;
    for (int j = idx; j < T_STEPS; j += stride) g_flag[j] = 0;
}

// ---------------- KA: neuron update (one block per batch row) ----------------
// Also folds in the pre-trace update with the PREVIOUS image (tr_t = bp*tr_{t-1} + img_{t-1}).
__global__ void __launch_bounds__(512) k_neuron(const float* __restrict__ img, int t,
                                                float* __restrict__ memrec,
                                                float* __restrict__ spkrec) {
    int b = blockIdx.x;
    int tid = threadIdx.x;

    __shared__ float simg[IN_SZ];
    __shared__ int   s_act[IN_SZ];
    __shared__ int   s_cnt;
    __shared__ int   s_win;
    __shared__ int   s_any;

    const float* imgt = img + ((size_t)t * B_SZ + b) * IN_SZ;
    if (t > 0) {
        const float* imgp = img + ((size_t)(t - 1) * B_SZ + b) * IN_SZ;
        for (int k = tid; k < IN_SZ; k += 512) {
            simg[k] = imgt[k];
            g_tr[b * IN_SZ + k] = BETA_PLUS * g_tr[b * IN_SZ + k] + imgp[k];
        }
    } else {
        for (int k = tid; k < IN_SZ; k += 512) simg[k] = imgt[k];
    }
    if (tid == 0) { s_win = INT_MAX; s_any = 0; }
    __syncthreads();

    // warp 0: order-preserving compaction of active input indices
    if (tid < 32) {
        int base = 0;
        for (int c = 0; c < (IN_SZ + 31) / 32; c++) {
            int k = c * 32 + tid;
            bool act = (k < IN_SZ) && (simg[k] != 0.0f);
            unsigned m = __ballot_sync(0xffffffffu, act);
            if (act) s_act[base + __popc(m & ((1u << tid) - 1u))] = k;
            base += __popc(m);
        }
        if (tid == 0) s_cnt = base;
    }
    __syncthreads();

    int cnt = s_cnt;
    if (tid < N_SZ) {
        int n = tid;
        float cur = 0.f;
        for (int i = 0; i < cnt; i++) cur += g_Wt[s_act[i] * N_SZ + n];

        float m = g_mem[b * N_SZ + n];
        float s = g_syn[b * N_SZ + n];
        float reset = (m > THRESH) ? 1.0f : 0.0f;
        s = ALPHA * s + cur;
        m = BETA * m + s - reset * THRESH;
        float spk = (m > THRESH) ? 1.0f : 0.0f;

        size_t rec = ((size_t)t * B_SZ + b) * N_SZ + n;
        memrec[rec] = m;
        spkrec[rec] = spk;
        g_syn[b * N_SZ + n] = s;
        g_mem[b * N_SZ + n] = m;

        if (spk != 0.f) { atomicMin(&s_win, n); s_any = 1; }
    }
    __syncthreads();
    if (tid == 0) {
        g_win[b] = (s_win == INT_MAX) ? 0 : s_win;
        if (s_any) atomicOr(&g_flag[t], 1);
    }
}

// ---------------- KB: lateral inhibition + post-trace update ----------------
__global__ void k_li_post(const float* __restrict__ spkrec, int t) {
    int idx = blockIdx.x * blockDim.x + threadIdx.x;
    if (idx >= B_SZ * N_SZ) return;
    int b = idx / N_SZ, n = idx % N_SZ;
    float spk = spkrec[(size_t)t * B_SZ * N_SZ + idx];
    if (g_flag[t]) {
        if (n != g_win[b]) g_syn[idx] -= LI_STR;
    }
    g_post[idx] = BETA_MINUS * g_post[idx] + spk;
}

// ---------------- KC: STDP weight update (two GEMMs over b, fused, with clamp) ----------------
// Wt[k,n] = clip(Wt[k,n] + A_PLUS*sum_b tr[b,k]*spk[b,n] - A_MINUS*sum_b img[b,k]*post[b,n], 0, 1)
// 64x64 output tile per block, 256 threads, 4x4 per thread, b in chunks of 16.
__global__ void __launch_bounds__(256) k_stdp(const float* __restrict__ img,
                                              const float* __restrict__ spkrec, int t) {
    __shared__ float sh_tr[16][64];
    __shared__ float sh_img[16][64];
    __shared__ float sh_spk[16][64];
    __shared__ float sh_post[16][64];

    int k0 = blockIdx.x * 64;
    int n0 = blockIdx.y * 64;
    int tx = threadIdx.x % 16;   // n sub-tile
    int ty = threadIdx.x / 16;   // k sub-tile

    float ltp[4][4], ltd[4][4];
#pragma unroll
    for (int i = 0; i < 4; i++)
#pragma unroll
        for (int j = 0; j < 4; j++) { ltp[i][j] = 0.f; ltd[i][j] = 0.f; }

    const float* imgt = img + (size_t)t * B_SZ * IN_SZ;
    const float* spkt = spkrec + (size_t)t * B_SZ * N_SZ;

    for (int b0 = 0; b0 < B_SZ; b0 += 16) {
        for (int i = threadIdx.x; i < 16 * 64; i += 256) {
            int bb = i / 64, c = i % 64;
            int k = k0 + c;
            float trv = 0.f, imv = 0.f;
            if (k < IN_SZ) {
                trv = g_tr[(b0 + bb) * IN_SZ + k];
                imv = imgt[(size_t)(b0 + bb) * IN_SZ + k];
            }
            sh_tr[bb][c] = trv;
            sh_img[bb][c] = imv;
            int n = n0 + c;
            float spv = 0.f, pov = 0.f;
            if (n < N_SZ) {
                spv = spkt[(b0 + bb) * N_SZ + n];
                pov = g_post[(b0 + bb) * N_SZ + n];
            }
            sh_spk[bb][c] = spv;
            sh_post[bb][c] = pov;
        }
        __syncthreads();

#pragma unroll
        for (int bb = 0; bb < 16; bb++) {
            float4 trv = *reinterpret_cast<const float4*>(&sh_tr[bb][ty * 4]);
            float4 imv = *reinterpret_cast<const float4*>(&sh_img[bb][ty * 4]);
            float4 spv = *reinterpret_cast<const float4*>(&sh_spk[bb][tx * 4]);
            float4 pov = *reinterpret_cast<const float4*>(&sh_post[bb][tx * 4]);
            float tr4[4] = {trv.x, trv.y, trv.z, trv.w};
            float im4[4] = {imv.x, imv.y, imv.z, imv.w};
            float sp4[4] = {spv.x, spv.y, spv.z, spv.w};
            float po4[4] = {pov.x, pov.y, pov.z, pov.w};
#pragma unroll
            for (int i = 0; i < 4; i++)
#pragma unroll
                for (int j = 0; j < 4; j++) {
                    ltp[i][j] += tr4[i] * sp4[j];
                    ltd[i][j] += im4[i] * po4[j];
                }
        }
        __syncthreads();
    }

#pragma unroll
    for (int i = 0; i < 4; i++) {
        int k = k0 + ty * 4 + i;
        if (k >= IN_SZ) continue;
#pragma unroll
        for (int j = 0; j < 4; j++) {
            int n = n0 + tx * 4 + j;
            if (n >= N_SZ) continue;
            float w = g_Wt[k * N_SZ + n];
            w = w + A_PLUS * ltp[i][j] - A_MINUS * ltd[i][j];
            w = fminf(fmaxf(w, 0.f), 1.f);
            g_Wt[k * N_SZ + n] = w;
        }
    }
}

// ---------------- final: transpose Wt back into output layout [N, IN] ----------------
__global__ void k_write_w(float* __restrict__ outW) {
    int idx = blockIdx.x * blockDim.x + threadIdx.x;
    if (idx >= N_SZ * IN_SZ) return;
    int n = idx / IN_SZ, k = idx % IN_SZ;
    outW[idx] = g_Wt[k * N_SZ + n];
}

// ---------------- launch ----------------
extern "C" void kernel_launch(void* const* d_in, const int* in_sizes, int n_in,
                              void* d_out, int out_size) {
    const float* img = (const float*)d_in[0];
    const float* W   = (const float*)d_in[1];
    // defensive: swap if metadata order differs
    if (n_in >= 2 && in_sizes[0] == N_SZ * IN_SZ) {
        const float* tmp = img; img = W; W = tmp;
    }

    float* out = (float*)d_out;
    float* memrec = out;
    float* spkrec = out + (size_t)T_STEPS * B_SZ * N_SZ;
    float* outW   = out + 2 * (size_t)T_STEPS * B_SZ * N_SZ;

    k_init<<<256, 256>>>(W);

    dim3 gridC((IN_SZ + 63) / 64, (N_SZ + 63) / 64);
    for (int t = 0; t < T_STEPS; t++) {
        k_neuron<<<B_SZ, 512>>>(img, t, memrec, spkrec);
        k_li_post<<<(B_SZ * N_SZ + 255) / 256, 256>>>(spkrec, t);
        k_stdp<<<gridC, 256>>>(img, spkrec, t);
    }
    k_write_w<<<(N_SZ * IN_SZ + 255) / 256, 256>>>(outW);
}